// round 11
// baseline (speedup 1.0000x reference)
#include <cuda_runtime.h>
#include <cuda_bf16.h>
#include <cuda_fp16.h>
#include <cstdint>

// Problem constants (fixed by the dataset)
#define NE 50000
#define NR 2000
#define EMAX 800000
#define NHEAD 8
#define DIM 128
#define NEG_SLOPE 0.01f
#define NSEG (2 * NE)
#define TILE 512
#define NTILES ((NSEG + TILE - 1) / TILE)   // 196

// grid partition for the fused prep kernel
#define ZBLK ((NSEG + 255) / 256)           // zero + detect
#define CVTBLK ((NR * DIM / 4 + 255) / 256) // x_r -> fp16
#define PEBLK (NE * 32 / 256)               // proj x_e
#define PRBLK (NR * 32 / 256)               // proj x_r

// ---------------- scratch (static device globals; no allocation) -------------
__device__ float g_ph[NE * NHEAD];      // x_e @ Wh.T
__device__ float g_pt[NE * NHEAD];      // x_e @ Wt.T
__device__ float g_pr[NR * NHEAD];      // x_r @ Wr.T
__device__ uint4 g_xrh4[NR * DIM / 8];  // x_r in fp16, 16 uint4 (256B) per row
__device__ int   g_deg[NSEG];           // degrees: [0,NE)=h side, [NE,2NE)=t side
__device__ int   g_coffs[NSEG + 1];     // exclusive offsets (combined h|t CSR)
__device__ int   g_elist[2 * EMAX];     // rel id per slot, grouped by (side,node)
__device__ int4  g_htr[EMAX];           // decoded (h, t, r, rank_h) per edge
__device__ int   g_rankt[EMAX];         // rank of edge within its t-side node
__device__ int   g_tsum[NTILES];        // per-tile degree sums
__device__ int   g_is64;                // 1 if edge_index/rel are int64

__device__ __forceinline__ float lrelu(float s) {
    return (s > 0.0f) ? s : NEG_SLOPE * s;
}

// ---------------- warp-per-row projection helper ------------------------------
__device__ __forceinline__ void proj_rows(const float* __restrict__ x,
                                          const float* __restrict__ Wa,
                                          const float* __restrict__ Wb,
                                          float* pa, float* pb, int bid) {
    int w = (bid * 256 + threadIdx.x) >> 5;
    int lane = threadIdx.x & 31;
    const float* xr = x + (long)w * DIM;
    float x0 = xr[lane], x1 = xr[lane + 32], x2 = xr[lane + 64], x3 = xr[lane + 96];
#pragma unroll
    for (int h = 0; h < NHEAD; h++) {
        const float* wa = Wa + h * DIM;
        float a = x0 * wa[lane] + x1 * wa[lane + 32] + x2 * wa[lane + 64] + x3 * wa[lane + 96];
#pragma unroll
        for (int off = 16; off > 0; off >>= 1) a += __shfl_xor_sync(0xffffffffu, a, off);
        if (lane == 0) pa[w * NHEAD + h] = a;
        if (pb) {
            const float* wb = Wb + h * DIM;
            float b = x0 * wb[lane] + x1 * wb[lane + 32] + x2 * wb[lane + 64] + x3 * wb[lane + 96];
#pragma unroll
            for (int off = 16; off > 0; off >>= 1) b += __shfl_xor_sync(0xffffffffu, b, off);
            if (lane == 0) pb[w * NHEAD + h] = b;
        }
    }
}

// ---------------- kernel 1: fused zero + detect + cvt + projections ----------
__global__ __launch_bounds__(256) void k_prep(const unsigned* __restrict__ ei_words,
                                              const float* __restrict__ x_e,
                                              const float* __restrict__ x_r,
                                              const float* __restrict__ Wh,
                                              const float* __restrict__ Wt,
                                              const float* __restrict__ Wr) {
    int bid = blockIdx.x;
    if (bid < ZBLK) {
        int i = bid * 256 + threadIdx.x;
        if (i < NSEG) g_deg[i] = 0;
        if (bid == 0 && threadIdx.x < 32) {
            unsigned w = ei_words[2 * threadIdx.x + 1];
            unsigned ball = __ballot_sync(0xffffffffu, w == 0u);
            if (threadIdx.x == 0) g_is64 = (ball == 0xffffffffu) ? 1 : 0;
        }
        return;
    }
    bid -= ZBLK;
    if (bid < CVTBLK) {
        int i = bid * 256 + threadIdx.x;
        if (i < NR * DIM / 4) {
            float4 v = ((const float4*)x_r)[i];
            __half2* dst = (__half2*)g_xrh4;
            dst[i * 2]     = __floats2half2_rn(v.x, v.y);
            dst[i * 2 + 1] = __floats2half2_rn(v.z, v.w);
        }
        return;
    }
    bid -= CVTBLK;
    if (bid < PEBLK) { proj_rows(x_e, Wh, Wt, g_ph, g_pt, bid); return; }
    bid -= PEBLK;
    proj_rows(x_r, Wr, nullptr, g_pr, nullptr, bid);
}

// ---------------- kernel 2: decode + histogram; KEEP the ranks ---------------
__global__ __launch_bounds__(256) void k_hist(const void* __restrict__ ei,
                                              const void* __restrict__ rel, int E) {
    int e = blockIdx.x * blockDim.x + threadIdx.x;
    if (e >= E) return;
    int is64 = g_is64;
    int h, t, r;
    if (is64) {
        h = (int)((const long long*)ei)[e];
        t = (int)((const long long*)ei)[(long)E + e];
        r = (int)((const long long*)rel)[e];
    } else {
        h = ((const int*)ei)[e];
        t = ((const int*)ei)[(long)E + e];
        r = ((const int*)rel)[e];
    }
    int rank_h = atomicAdd(&g_deg[h], 1);        // rank within h-side node
    int rank_t = atomicAdd(&g_deg[NE + t], 1);   // rank within t-side node
    g_htr[e] = make_int4(h, t, r, rank_h);
    g_rankt[e] = rank_t;
}

// ---------------- kernel 3a: per-tile degree sums -----------------------------
__global__ __launch_bounds__(256) void k_scan_a() {
    __shared__ int sh[256];
    int tid = threadIdx.x;
    int i0 = blockIdx.x * TILE + tid * 2;
    int v = 0;
    if (i0 < NSEG) v += g_deg[i0];
    if (i0 + 1 < NSEG) v += g_deg[i0 + 1];
    sh[tid] = v;
    __syncthreads();
    for (int off = 128; off > 0; off >>= 1) {
        if (tid < off) sh[tid] += sh[tid + off];
        __syncthreads();
    }
    if (tid == 0) g_tsum[blockIdx.x] = sh[0];
}

// ---------------- kernel 3b: tile scan with embedded top-level scan ----------
__global__ __launch_bounds__(512) void k_scan_c(int E) {
    __shared__ int stop[256];
    __shared__ int stile[512];
    int tid = threadIdx.x;
    // redundant top-level inclusive scan of tile sums in every block (cheap)
    if (tid < 256) stop[tid] = (tid < NTILES) ? g_tsum[tid] : 0;
    __syncthreads();
    for (int off = 1; off < 256; off <<= 1) {
        int t = 0;
        if (tid < 256 && tid >= off) t = stop[tid - off];
        __syncthreads();
        if (tid < 256) stop[tid] += t;
        __syncthreads();
    }
    int tile_off = (blockIdx.x == 0) ? 0 : stop[blockIdx.x - 1];
    // local scan of this 512-entry tile
    int idx = blockIdx.x * TILE + tid;
    int v = (idx < NSEG) ? g_deg[idx] : 0;
    stile[tid] = v;
    __syncthreads();
    for (int off = 1; off < 512; off <<= 1) {
        int t = 0;
        if (tid >= off) t = stile[tid - off];
        __syncthreads();
        stile[tid] += t;
        __syncthreads();
    }
    if (idx < NSEG) g_coffs[idx] = tile_off + stile[tid] - v;
    if (blockIdx.x == 0 && tid == 0) g_coffs[NSEG] = 2 * E;
}

// ---------------- kernel 4: rank-based scatter (NO atomics) ------------------
__global__ __launch_bounds__(256) void k_fill(int E) {
    int e = blockIdx.x * blockDim.x + threadIdx.x;
    if (e >= E) return;
    int4 v = g_htr[e];                 // (h, t, r, rank_h)
    int rt = g_rankt[e];
    g_elist[g_coffs[v.x] + v.w] = v.z;
    g_elist[g_coffs[NE + v.y] + rt] = v.z;
}

// ---------------- kernel 5: softmax + aggregation (fp16 x_r gather) ----------
// One warp per (side, node). Recompute alphas in phase 2; 4 edges/iter via
// 8-lane groups; x_r gathered as fp16. __launch_bounds__(256,4) caps regs at
// 64 to double resident warps (occupancy was the suspected binder).
__global__ __launch_bounds__(256, 4) void k_agg(float* __restrict__ out) {
    __shared__ __align__(16) float s_out[8][128];
    int wslot = threadIdx.x >> 5;
    int gw = (blockIdx.x * blockDim.x + threadIdx.x) >> 5;
    int lane = threadIdx.x & 31;
    if (gw >= NSEG) return;
    int side = (gw >= NE) ? 1 : 0;
    int node = side ? (gw - NE) : gw;
    const float* p = side ? g_pt : g_ph;

    int start = g_coffs[gw];
    int end = g_coffs[gw + 1];

    const float4* pn4 = (const float4*)(p + node * NHEAD);
    float4 pnA = pn4[0], pnB = pn4[1];
    float pn[NHEAD] = {pnA.x, pnA.y, pnA.z, pnA.w, pnB.x, pnB.y, pnB.z, pnB.w};

    // ---- phase 1: denominators per head -------------------------------------
    float exs[NHEAD];
#pragma unroll
    for (int h = 0; h < NHEAD; h++) exs[h] = 0.0f;
    for (int j = start + lane; j < end; j += 32) {
        int r = g_elist[j];
        const float4* pr4 = (const float4*)(g_pr + r * NHEAD);
        float4 A = pr4[0], B = pr4[1];
        exs[0] += __expf(lrelu(pn[0] + A.x));
        exs[1] += __expf(lrelu(pn[1] + A.y));
        exs[2] += __expf(lrelu(pn[2] + A.z));
        exs[3] += __expf(lrelu(pn[3] + A.w));
        exs[4] += __expf(lrelu(pn[4] + B.x));
        exs[5] += __expf(lrelu(pn[5] + B.y));
        exs[6] += __expf(lrelu(pn[6] + B.z));
        exs[7] += __expf(lrelu(pn[7] + B.w));
    }
#pragma unroll
    for (int h = 0; h < NHEAD; h++) {
        float v = exs[h];
#pragma unroll
        for (int off = 16; off > 0; off >>= 1) v += __shfl_xor_sync(0xffffffffu, v, off);
        exs[h] = v;
    }

    int myh = lane & 7;
    int myg = lane >> 3;
    float pn_my = 0.0f, den_my = 0.0f;
#pragma unroll
    for (int h = 0; h < NHEAD; h++) {
        pn_my = (myh == h) ? pn[h] : pn_my;
        den_my = (myh == h) ? exs[h] : den_my;
    }
    float invd_my = 1.0f / (den_my + 1e-16f);

    // ---- phase 2: 4 edges/iter via 8-lane groups; fp16 row gathers ----------
    float accA[8], accB[8];
#pragma unroll
    for (int i = 0; i < 8; i++) { accA[i] = 0.0f; accB[i] = 0.0f; }

#define PROC4(BASE)                                                            \
    {                                                                          \
        int r = g_elist[(BASE) + myg];                                         \
        float ex = __expf(lrelu(pn_my + g_pr[r * NHEAD + myh])) * invd_my;     \
        ex += __shfl_xor_sync(0xffffffffu, ex, 1);                             \
        ex += __shfl_xor_sync(0xffffffffu, ex, 2);                             \
        ex += __shfl_xor_sync(0xffffffffu, ex, 4);                             \
        float a = ex * 0.125f;                                                 \
        const uint4* row = g_xrh4 + r * 16;                                    \
        uint4 u0 = row[myh];                                                   \
        uint4 u1 = row[myh + 8];                                               \
        float2 q;                                                              \
        q = __half22float2(*(__half2*)&u0.x); accA[0] += a * q.x; accA[1] += a * q.y; \
        q = __half22float2(*(__half2*)&u0.y); accA[2] += a * q.x; accA[3] += a * q.y; \
        q = __half22float2(*(__half2*)&u0.z); accA[4] += a * q.x; accA[5] += a * q.y; \
        q = __half22float2(*(__half2*)&u0.w); accA[6] += a * q.x; accA[7] += a * q.y; \
        q = __half22float2(*(__half2*)&u1.x); accB[0] += a * q.x; accB[1] += a * q.y; \
        q = __half22float2(*(__half2*)&u1.y); accB[2] += a * q.x; accB[3] += a * q.y; \
        q = __half22float2(*(__half2*)&u1.z); accB[4] += a * q.x; accB[5] += a * q.y; \
        q = __half22float2(*(__half2*)&u1.w); accB[6] += a * q.x; accB[7] += a * q.y; \
    }

    int jb = start;
    for (; jb + 8 <= end; jb += 8) {
        PROC4(jb)
        PROC4(jb + 4)
    }
    if (jb + 4 <= end) {
        PROC4(jb)
        jb += 4;
    }
#undef PROC4

    // reduce accumulators across the 4 groups (xor 8, 16)
#pragma unroll
    for (int i = 0; i < 8; i++) {
        accA[i] += __shfl_xor_sync(0xffffffffu, accA[i], 8);
        accA[i] += __shfl_xor_sync(0xffffffffu, accA[i], 16);
        accB[i] += __shfl_xor_sync(0xffffffffu, accB[i], 8);
        accB[i] += __shfl_xor_sync(0xffffffffu, accB[i], 16);
    }

    // remap to per-lane float4 layout via shared staging
    if (myg == 0) {          // lanes 0..7, myh == lane
        float* so = s_out[wslot];
#pragma unroll
        for (int i = 0; i < 8; i++) so[8 * lane + i] = accA[i];
#pragma unroll
        for (int i = 0; i < 8; i++) so[64 + 8 * lane + i] = accB[i];
    }
    __syncwarp();
    float4 res = *(const float4*)&s_out[wslot][4 * lane];

    // tail (0..3 edges): whole-warp, each lane loads its own 4 columns (8B)
    for (; jb < end; jb++) {
        int r = g_elist[jb];                      // uniform -> broadcast
        float ex = __expf(lrelu(pn_my + g_pr[r * NHEAD + myh])) * invd_my;
        ex += __shfl_xor_sync(0xffffffffu, ex, 1);
        ex += __shfl_xor_sync(0xffffffffu, ex, 2);
        ex += __shfl_xor_sync(0xffffffffu, ex, 4);
        float a = ex * 0.125f;
        const uint2* row2 = (const uint2*)(g_xrh4 + r * 16);
        uint2 u = row2[lane];
        float2 qa = __half22float2(*(__half2*)&u.x);
        float2 qb = __half22float2(*(__half2*)&u.y);
        res.x += a * qa.x;
        res.y += a * qa.y;
        res.z += a * qb.x;
        res.w += a * qb.y;
    }

    // streaming store: keep hot structures resident in L2
    __stcs((float4*)(out + (long)node * (2 * DIM) + side * DIM) + lane, res);
}

// ---------------- launch ------------------------------------------------------
extern "C" void kernel_launch(void* const* d_in, const int* in_sizes, int n_in,
                              void* d_out, int out_size) {
    const float* x_e = (const float*)d_in[0];
    const float* x_r = (const float*)d_in[1];
    const float* Wh  = (const float*)d_in[2];
    const float* Wt  = (const float*)d_in[3];
    const float* Wr  = (const float*)d_in[4];
    const void*  ei  = d_in[5];
    const void*  rel = d_in[6];
    int E = in_sizes[6];          // element count of rel == number of edges

    k_prep<<<ZBLK + CVTBLK + PEBLK + PRBLK, 256>>>((const unsigned*)ei, x_e, x_r,
                                                   Wh, Wt, Wr);

    k_hist<<<(E + 255) / 256, 256>>>(ei, rel, E);

    k_scan_a<<<NTILES, 256>>>();
    k_scan_c<<<NTILES, 512>>>(E);

    k_fill<<<(E + 255) / 256, 256>>>(E);

    k_agg<<<(NSEG * 32 + 255) / 256, 256>>>((float*)d_out);
}

// round 12
// speedup vs baseline: 1.0203x; 1.0203x over previous
#include <cuda_runtime.h>
#include <cuda_bf16.h>
#include <cuda_fp16.h>
#include <cstdint>

// Problem constants (fixed by the dataset)
#define NE 50000
#define NR 2000
#define EMAX 800000
#define NHEAD 8
#define DIM 128
#define NEG_SLOPE 0.01f
#define NSEG (2 * NE)
#define TILE 512
#define NTILES ((NSEG + TILE - 1) / TILE)   // 196

// grid partition for the fused prep kernel
#define ZBLK ((NSEG + 255) / 256)           // zero + detect
#define CVTBLK ((NR * DIM / 4 + 255) / 256) // x_r -> fp16
#define PEBLK (NE * 32 / 256)               // proj x_e
#define PRBLK (NR * 32 / 256)               // proj x_r

// ---------------- scratch (static device globals; no allocation) -------------
__device__ float g_ph[NE * NHEAD];      // x_e @ Wh.T
__device__ float g_pt[NE * NHEAD];      // x_e @ Wt.T
__device__ float g_pr[NR * NHEAD];      // x_r @ Wr.T
__device__ uint4 g_xrh4[NR * DIM / 8];  // x_r in fp16, 16 uint4 (256B) per row
__device__ int   g_deg[NSEG];           // degrees: [0,NE)=h side, [NE,2NE)=t side
__device__ int   g_coffs[NSEG + 1];     // exclusive offsets (combined h|t CSR)
__device__ int   g_elist[2 * EMAX];     // rel id per slot, grouped by (side,node)
__device__ int4  g_htr[EMAX];           // decoded (h, t, r, rank_h) per edge
__device__ int   g_rankt[EMAX];         // rank of edge within its t-side node
__device__ int   g_tsum[NTILES];        // per-tile degree sums
__device__ int   g_is64;                // 1 if edge_index/rel are int64

__device__ __forceinline__ float lrelu(float s) {
    return (s > 0.0f) ? s : NEG_SLOPE * s;
}

// ---------------- warp-per-row projection helper ------------------------------
__device__ __forceinline__ void proj_rows(const float* __restrict__ x,
                                          const float* __restrict__ Wa,
                                          const float* __restrict__ Wb,
                                          float* pa, float* pb, int bid) {
    int w = (bid * 256 + threadIdx.x) >> 5;
    int lane = threadIdx.x & 31;
    const float* xr = x + (long)w * DIM;
    float x0 = xr[lane], x1 = xr[lane + 32], x2 = xr[lane + 64], x3 = xr[lane + 96];
#pragma unroll
    for (int h = 0; h < NHEAD; h++) {
        const float* wa = Wa + h * DIM;
        float a = x0 * wa[lane] + x1 * wa[lane + 32] + x2 * wa[lane + 64] + x3 * wa[lane + 96];
#pragma unroll
        for (int off = 16; off > 0; off >>= 1) a += __shfl_xor_sync(0xffffffffu, a, off);
        if (lane == 0) pa[w * NHEAD + h] = a;
        if (pb) {
            const float* wb = Wb + h * DIM;
            float b = x0 * wb[lane] + x1 * wb[lane + 32] + x2 * wb[lane + 64] + x3 * wb[lane + 96];
#pragma unroll
            for (int off = 16; off > 0; off >>= 1) b += __shfl_xor_sync(0xffffffffu, b, off);
            if (lane == 0) pb[w * NHEAD + h] = b;
        }
    }
}

// ---------------- kernel 1: fused zero + detect + cvt + projections ----------
__global__ __launch_bounds__(256) void k_prep(const unsigned* __restrict__ ei_words,
                                              const float* __restrict__ x_e,
                                              const float* __restrict__ x_r,
                                              const float* __restrict__ Wh,
                                              const float* __restrict__ Wt,
                                              const float* __restrict__ Wr) {
    int bid = blockIdx.x;
    if (bid < ZBLK) {
        int i = bid * 256 + threadIdx.x;
        if (i < NSEG) g_deg[i] = 0;
        if (bid == 0 && threadIdx.x < 32) {
            unsigned w = ei_words[2 * threadIdx.x + 1];
            unsigned ball = __ballot_sync(0xffffffffu, w == 0u);
            if (threadIdx.x == 0) g_is64 = (ball == 0xffffffffu) ? 1 : 0;
        }
        return;
    }
    bid -= ZBLK;
    if (bid < CVTBLK) {
        int i = bid * 256 + threadIdx.x;
        if (i < NR * DIM / 4) {
            float4 v = ((const float4*)x_r)[i];
            __half2* dst = (__half2*)g_xrh4;
            dst[i * 2]     = __floats2half2_rn(v.x, v.y);
            dst[i * 2 + 1] = __floats2half2_rn(v.z, v.w);
        }
        return;
    }
    bid -= CVTBLK;
    if (bid < PEBLK) { proj_rows(x_e, Wh, Wt, g_ph, g_pt, bid); return; }
    bid -= PEBLK;
    proj_rows(x_r, Wr, nullptr, g_pr, nullptr, bid);
}

// ---------------- kernel 2: decode + histogram; KEEP the ranks ---------------
__global__ __launch_bounds__(256) void k_hist(const void* __restrict__ ei,
                                              const void* __restrict__ rel, int E) {
    int e = blockIdx.x * blockDim.x + threadIdx.x;
    if (e >= E) return;
    int is64 = g_is64;
    int h, t, r;
    if (is64) {
        h = (int)((const long long*)ei)[e];
        t = (int)((const long long*)ei)[(long)E + e];
        r = (int)((const long long*)rel)[e];
    } else {
        h = ((const int*)ei)[e];
        t = ((const int*)ei)[(long)E + e];
        r = ((const int*)rel)[e];
    }
    int rank_h = atomicAdd(&g_deg[h], 1);        // rank within h-side node
    int rank_t = atomicAdd(&g_deg[NE + t], 1);   // rank within t-side node
    g_htr[e] = make_int4(h, t, r, rank_h);
    g_rankt[e] = rank_t;
}

// ---------------- kernel 3a: per-tile degree sums -----------------------------
__global__ __launch_bounds__(256) void k_scan_a() {
    __shared__ int sh[256];
    int tid = threadIdx.x;
    int i0 = blockIdx.x * TILE + tid * 2;
    int v = 0;
    if (i0 < NSEG) v += g_deg[i0];
    if (i0 + 1 < NSEG) v += g_deg[i0 + 1];
    sh[tid] = v;
    __syncthreads();
    for (int off = 128; off > 0; off >>= 1) {
        if (tid < off) sh[tid] += sh[tid + off];
        __syncthreads();
    }
    if (tid == 0) g_tsum[blockIdx.x] = sh[0];
}

// ---------------- kernel 3b: tile scan with embedded top-level scan ----------
__global__ __launch_bounds__(512) void k_scan_c(int E) {
    __shared__ int stop[256];
    __shared__ int stile[512];
    int tid = threadIdx.x;
    // redundant top-level inclusive scan of tile sums in every block (cheap)
    if (tid < 256) stop[tid] = (tid < NTILES) ? g_tsum[tid] : 0;
    __syncthreads();
    for (int off = 1; off < 256; off <<= 1) {
        int t = 0;
        if (tid < 256 && tid >= off) t = stop[tid - off];
        __syncthreads();
        if (tid < 256) stop[tid] += t;
        __syncthreads();
    }
    int tile_off = (blockIdx.x == 0) ? 0 : stop[blockIdx.x - 1];
    // local scan of this 512-entry tile
    int idx = blockIdx.x * TILE + tid;
    int v = (idx < NSEG) ? g_deg[idx] : 0;
    stile[tid] = v;
    __syncthreads();
    for (int off = 1; off < 512; off <<= 1) {
        int t = 0;
        if (tid >= off) t = stile[tid - off];
        __syncthreads();
        stile[tid] += t;
        __syncthreads();
    }
    if (idx < NSEG) g_coffs[idx] = tile_off + stile[tid] - v;
    if (blockIdx.x == 0 && tid == 0) g_coffs[NSEG] = 2 * E;
}

// ---------------- kernel 4: rank-based scatter (NO atomics) ------------------
__global__ __launch_bounds__(256) void k_fill(int E) {
    int e = blockIdx.x * blockDim.x + threadIdx.x;
    if (e >= E) return;
    int4 v = g_htr[e];                 // (h, t, r, rank_h)
    int rt = g_rankt[e];
    g_elist[g_coffs[v.x] + v.w] = v.z;
    g_elist[g_coffs[NE + v.y] + rt] = v.z;
}

// ---------------- kernel 5: softmax + aggregation (fp16 x_r gather) ----------
// One warp per (side, node). Recompute alphas in phase 2; 4 edges/iter via
// 8-lane groups; x_r gathered as fp16. Natural register allocation (the
// (256,4) occupancy cap in R11 regressed: spills cost more than warps bought).
__global__ __launch_bounds__(256) void k_agg(float* __restrict__ out) {
    __shared__ __align__(16) float s_out[8][128];
    int wslot = threadIdx.x >> 5;
    int gw = (blockIdx.x * blockDim.x + threadIdx.x) >> 5;
    int lane = threadIdx.x & 31;
    if (gw >= NSEG) return;
    int side = (gw >= NE) ? 1 : 0;
    int node = side ? (gw - NE) : gw;
    const float* p = side ? g_pt : g_ph;

    int start = g_coffs[gw];
    int end = g_coffs[gw + 1];

    const float4* pn4 = (const float4*)(p + node * NHEAD);
    float4 pnA = pn4[0], pnB = pn4[1];
    float pn[NHEAD] = {pnA.x, pnA.y, pnA.z, pnA.w, pnB.x, pnB.y, pnB.z, pnB.w};

    // ---- phase 1: denominators per head -------------------------------------
    float exs[NHEAD];
#pragma unroll
    for (int h = 0; h < NHEAD; h++) exs[h] = 0.0f;
    for (int j = start + lane; j < end; j += 32) {
        int r = g_elist[j];
        const float4* pr4 = (const float4*)(g_pr + r * NHEAD);
        float4 A = pr4[0], B = pr4[1];
        exs[0] += __expf(lrelu(pn[0] + A.x));
        exs[1] += __expf(lrelu(pn[1] + A.y));
        exs[2] += __expf(lrelu(pn[2] + A.z));
        exs[3] += __expf(lrelu(pn[3] + A.w));
        exs[4] += __expf(lrelu(pn[4] + B.x));
        exs[5] += __expf(lrelu(pn[5] + B.y));
        exs[6] += __expf(lrelu(pn[6] + B.z));
        exs[7] += __expf(lrelu(pn[7] + B.w));
    }
#pragma unroll
    for (int h = 0; h < NHEAD; h++) {
        float v = exs[h];
#pragma unroll
        for (int off = 16; off > 0; off >>= 1) v += __shfl_xor_sync(0xffffffffu, v, off);
        exs[h] = v;
    }

    int myh = lane & 7;
    int myg = lane >> 3;
    float pn_my = 0.0f, den_my = 0.0f;
#pragma unroll
    for (int h = 0; h < NHEAD; h++) {
        pn_my = (myh == h) ? pn[h] : pn_my;
        den_my = (myh == h) ? exs[h] : den_my;
    }
    float invd_my = 1.0f / (den_my + 1e-16f);

    // ---- phase 2: 4 edges/iter via 8-lane groups; fp16 row gathers ----------
    float accA[8], accB[8];
#pragma unroll
    for (int i = 0; i < 8; i++) { accA[i] = 0.0f; accB[i] = 0.0f; }

#define PROC4(BASE)                                                            \
    {                                                                          \
        int r = g_elist[(BASE) + myg];                                         \
        float ex = __expf(lrelu(pn_my + g_pr[r * NHEAD + myh])) * invd_my;     \
        ex += __shfl_xor_sync(0xffffffffu, ex, 1);                             \
        ex += __shfl_xor_sync(0xffffffffu, ex, 2);                             \
        ex += __shfl_xor_sync(0xffffffffu, ex, 4);                             \
        float a = ex * 0.125f;                                                 \
        const uint4* row = g_xrh4 + r * 16;                                    \
        uint4 u0 = row[myh];                                                   \
        uint4 u1 = row[myh + 8];                                               \
        float2 q;                                                              \
        q = __half22float2(*(__half2*)&u0.x); accA[0] += a * q.x; accA[1] += a * q.y; \
        q = __half22float2(*(__half2*)&u0.y); accA[2] += a * q.x; accA[3] += a * q.y; \
        q = __half22float2(*(__half2*)&u0.z); accA[4] += a * q.x; accA[5] += a * q.y; \
        q = __half22float2(*(__half2*)&u0.w); accA[6] += a * q.x; accA[7] += a * q.y; \
        q = __half22float2(*(__half2*)&u1.x); accB[0] += a * q.x; accB[1] += a * q.y; \
        q = __half22float2(*(__half2*)&u1.y); accB[2] += a * q.x; accB[3] += a * q.y; \
        q = __half22float2(*(__half2*)&u1.z); accB[4] += a * q.x; accB[5] += a * q.y; \
        q = __half22float2(*(__half2*)&u1.w); accB[6] += a * q.x; accB[7] += a * q.y; \
    }

    int jb = start;
    for (; jb + 8 <= end; jb += 8) {
        PROC4(jb)
        PROC4(jb + 4)
    }
    if (jb + 4 <= end) {
        PROC4(jb)
        jb += 4;
    }
#undef PROC4

    // reduce accumulators across the 4 groups (xor 8, 16)
#pragma unroll
    for (int i = 0; i < 8; i++) {
        accA[i] += __shfl_xor_sync(0xffffffffu, accA[i], 8);
        accA[i] += __shfl_xor_sync(0xffffffffu, accA[i], 16);
        accB[i] += __shfl_xor_sync(0xffffffffu, accB[i], 8);
        accB[i] += __shfl_xor_sync(0xffffffffu, accB[i], 16);
    }

    // remap to per-lane float4 layout via shared staging
    if (myg == 0) {          // lanes 0..7, myh == lane
        float* so = s_out[wslot];
#pragma unroll
        for (int i = 0; i < 8; i++) so[8 * lane + i] = accA[i];
#pragma unroll
        for (int i = 0; i < 8; i++) so[64 + 8 * lane + i] = accB[i];
    }
    __syncwarp();
    float4 res = *(const float4*)&s_out[wslot][4 * lane];

    // tail (0..3 edges): whole-warp, each lane loads its own 4 columns (8B)
    for (; jb < end; jb++) {
        int r = g_elist[jb];                      // uniform -> broadcast
        float ex = __expf(lrelu(pn_my + g_pr[r * NHEAD + myh])) * invd_my;
        ex += __shfl_xor_sync(0xffffffffu, ex, 1);
        ex += __shfl_xor_sync(0xffffffffu, ex, 2);
        ex += __shfl_xor_sync(0xffffffffu, ex, 4);
        float a = ex * 0.125f;
        const uint2* row2 = (const uint2*)(g_xrh4 + r * 16);
        uint2 u = row2[lane];
        float2 qa = __half22float2(*(__half2*)&u.x);
        float2 qb = __half22float2(*(__half2*)&u.y);
        res.x += a * qa.x;
        res.y += a * qa.y;
        res.z += a * qb.x;
        res.w += a * qb.y;
    }

    // streaming store: keep hot structures resident in L2
    __stcs((float4*)(out + (long)node * (2 * DIM) + side * DIM) + lane, res);
}

// ---------------- launch ------------------------------------------------------
extern "C" void kernel_launch(void* const* d_in, const int* in_sizes, int n_in,
                              void* d_out, int out_size) {
    const float* x_e = (const float*)d_in[0];
    const float* x_r = (const float*)d_in[1];
    const float* Wh  = (const float*)d_in[2];
    const float* Wt  = (const float*)d_in[3];
    const float* Wr  = (const float*)d_in[4];
    const void*  ei  = d_in[5];
    const void*  rel = d_in[6];
    int E = in_sizes[6];          // element count of rel == number of edges

    k_prep<<<ZBLK + CVTBLK + PEBLK + PRBLK, 256>>>((const unsigned*)ei, x_e, x_r,
                                                   Wh, Wt, Wr);

    k_hist<<<(E + 255) / 256, 256>>>(ei, rel, E);

    k_scan_a<<<NTILES, 256>>>();
    k_scan_c<<<NTILES, 512>>>(E);

    k_fill<<<(E + 255) / 256, 256>>>(E);

    k_agg<<<(NSEG * 32 + 255) / 256, 256>>>((float*)d_out);
}

// round 13
// speedup vs baseline: 1.0514x; 1.0305x over previous
#include <cuda_runtime.h>
#include <cuda_bf16.h>
#include <cuda_fp16.h>
#include <cstdint>

// Problem constants (fixed by the dataset)
#define NE 50000
#define NR 2000
#define EMAX 800000
#define NHEAD 8
#define DIM 128
#define NEG_SLOPE 0.01f
#define NSEG (2 * NE)
#define TILE 512
#define NTILES ((NSEG + TILE - 1) / TILE)   // 196

// grid partition for the fused prep kernel
#define ZBLK ((NSEG + 255) / 256)           // zero + detect
#define CVTBLK ((NR * DIM / 4 + 255) / 256) // x_r -> fp16
#define PEBLK (NE * 32 / 256)               // proj x_e
#define PRBLK (NR * 32 / 256)               // proj x_r

// ---------------- scratch (static device globals; no allocation) -------------
__device__ float g_ph[NE * NHEAD];      // x_e @ Wh.T
__device__ float g_pt[NE * NHEAD];      // x_e @ Wt.T
__device__ float g_pr[NR * NHEAD];      // x_r @ Wr.T
__device__ uint4 g_xrh4[NR * DIM / 8];  // x_r in fp16, 16 uint4 (256B) per row
__device__ int   g_deg[NSEG];           // degrees: [0,NE)=h side, [NE,2NE)=t side
__device__ int   g_coffs[NSEG + 1];     // exclusive offsets (combined h|t CSR)
__device__ int   g_elist[2 * EMAX];     // rel id per slot, grouped by (side,node)
__device__ int4  g_htr[EMAX];           // (h, t, r, rank_h | rank_t<<16)
__device__ int   g_tsum[NTILES];        // per-tile degree sums
__device__ int   g_is64;                // 1 if edge_index/rel are int64

__device__ __forceinline__ float lrelu(float s) {
    return (s > 0.0f) ? s : NEG_SLOPE * s;
}

// ---------------- warp-per-row projection helper ------------------------------
__device__ __forceinline__ void proj_rows(const float* __restrict__ x,
                                          const float* __restrict__ Wa,
                                          const float* __restrict__ Wb,
                                          float* pa, float* pb, int bid) {
    int w = (bid * 256 + threadIdx.x) >> 5;
    int lane = threadIdx.x & 31;
    const float* xr = x + (long)w * DIM;
    float x0 = xr[lane], x1 = xr[lane + 32], x2 = xr[lane + 64], x3 = xr[lane + 96];
#pragma unroll
    for (int h = 0; h < NHEAD; h++) {
        const float* wa = Wa + h * DIM;
        float a = x0 * wa[lane] + x1 * wa[lane + 32] + x2 * wa[lane + 64] + x3 * wa[lane + 96];
#pragma unroll
        for (int off = 16; off > 0; off >>= 1) a += __shfl_xor_sync(0xffffffffu, a, off);
        if (lane == 0) pa[w * NHEAD + h] = a;
        if (pb) {
            const float* wb = Wb + h * DIM;
            float b = x0 * wb[lane] + x1 * wb[lane + 32] + x2 * wb[lane + 64] + x3 * wb[lane + 96];
#pragma unroll
            for (int off = 16; off > 0; off >>= 1) b += __shfl_xor_sync(0xffffffffu, b, off);
            if (lane == 0) pb[w * NHEAD + h] = b;
        }
    }
}

// ---------------- kernel 1: fused zero + detect + cvt + projections ----------
__global__ __launch_bounds__(256) void k_prep(const unsigned* __restrict__ ei_words,
                                              const float* __restrict__ x_e,
                                              const float* __restrict__ x_r,
                                              const float* __restrict__ Wh,
                                              const float* __restrict__ Wt,
                                              const float* __restrict__ Wr) {
    int bid = blockIdx.x;
    if (bid < ZBLK) {
        int i = bid * 256 + threadIdx.x;
        if (i < NSEG) g_deg[i] = 0;
        if (bid == 0 && threadIdx.x < 32) {
            unsigned w = ei_words[2 * threadIdx.x + 1];
            unsigned ball = __ballot_sync(0xffffffffu, w == 0u);
            if (threadIdx.x == 0) g_is64 = (ball == 0xffffffffu) ? 1 : 0;
        }
        return;
    }
    bid -= ZBLK;
    if (bid < CVTBLK) {
        int i = bid * 256 + threadIdx.x;
        if (i < NR * DIM / 4) {
            float4 v = ((const float4*)x_r)[i];
            __half2* dst = (__half2*)g_xrh4;
            dst[i * 2]     = __floats2half2_rn(v.x, v.y);
            dst[i * 2 + 1] = __floats2half2_rn(v.z, v.w);
        }
        return;
    }
    bid -= CVTBLK;
    if (bid < PEBLK) { proj_rows(x_e, Wh, Wt, g_ph, g_pt, bid); return; }
    bid -= PEBLK;
    proj_rows(x_r, Wr, nullptr, g_pr, nullptr, bid);
}

// ---------------- kernel 2: decode + histogram; ranks packed in .w -----------
__global__ __launch_bounds__(256) void k_hist(const void* __restrict__ ei,
                                              const void* __restrict__ rel, int E) {
    int e = blockIdx.x * blockDim.x + threadIdx.x;
    if (e >= E) return;
    int is64 = g_is64;
    int h, t, r;
    if (is64) {
        h = (int)((const long long*)ei)[e];
        t = (int)((const long long*)ei)[(long)E + e];
        r = (int)((const long long*)rel)[e];
    } else {
        h = ((const int*)ei)[e];
        t = ((const int*)ei)[(long)E + e];
        r = ((const int*)rel)[e];
    }
    int rank_h = atomicAdd(&g_deg[h], 1);        // rank within h-side node
    int rank_t = atomicAdd(&g_deg[NE + t], 1);   // rank within t-side node
    g_htr[e] = make_int4(h, t, r, rank_h | (rank_t << 16));
}

// ---------------- kernel 3a: per-tile degree sums -----------------------------
__global__ __launch_bounds__(256) void k_scan_a() {
    __shared__ int sh[256];
    int tid = threadIdx.x;
    int i0 = blockIdx.x * TILE + tid * 2;
    int v = 0;
    if (i0 < NSEG) v += g_deg[i0];
    if (i0 + 1 < NSEG) v += g_deg[i0 + 1];
    sh[tid] = v;
    __syncthreads();
    for (int off = 128; off > 0; off >>= 1) {
        if (tid < off) sh[tid] += sh[tid + off];
        __syncthreads();
    }
    if (tid == 0) g_tsum[blockIdx.x] = sh[0];
}

// ---------------- kernel 3b: tile scan with embedded top-level scan ----------
__global__ __launch_bounds__(512) void k_scan_c(int E) {
    __shared__ int stop[256];
    __shared__ int stile[512];
    int tid = threadIdx.x;
    if (tid < 256) stop[tid] = (tid < NTILES) ? g_tsum[tid] : 0;
    __syncthreads();
    for (int off = 1; off < 256; off <<= 1) {
        int t = 0;
        if (tid < 256 && tid >= off) t = stop[tid - off];
        __syncthreads();
        if (tid < 256) stop[tid] += t;
        __syncthreads();
    }
    int tile_off = (blockIdx.x == 0) ? 0 : stop[blockIdx.x - 1];
    int idx = blockIdx.x * TILE + tid;
    int v = (idx < NSEG) ? g_deg[idx] : 0;
    stile[tid] = v;
    __syncthreads();
    for (int off = 1; off < 512; off <<= 1) {
        int t = 0;
        if (tid >= off) t = stile[tid - off];
        __syncthreads();
        stile[tid] += t;
        __syncthreads();
    }
    if (idx < NSEG) g_coffs[idx] = tile_off + stile[tid] - v;
    if (blockIdx.x == 0 && tid == 0) g_coffs[NSEG] = 2 * E;
}

// ---------------- kernel 4: rank-based scatter (NO atomics) ------------------
__global__ __launch_bounds__(256) void k_fill(int E) {
    int e = blockIdx.x * blockDim.x + threadIdx.x;
    if (e >= E) return;
    int4 v = g_htr[e];                 // (h, t, r, rank_h | rank_t<<16)
    int rh = v.w & 0xFFFF;
    int rt = v.w >> 16;
    g_elist[g_coffs[v.x] + rh] = v.z;
    g_elist[g_coffs[NE + v.y] + rt] = v.z;
}

// ---------------- kernel 5: softmax + aggregation (fp16 x_r gather) ----------
// One warp per (side, node), 128-thread blocks: halves regs/block so 4-6
// blocks fit per SM (vs 2 at 256 threads) -> +50% resident warps without
// forcing spills (R11's mistake). Kernel body unchanged from R12.
__global__ __launch_bounds__(128) void k_agg(float* __restrict__ out) {
    __shared__ __align__(16) float s_out[4][128];
    int wslot = threadIdx.x >> 5;
    int gw = (blockIdx.x * blockDim.x + threadIdx.x) >> 5;
    int lane = threadIdx.x & 31;
    if (gw >= NSEG) return;
    int side = (gw >= NE) ? 1 : 0;
    int node = side ? (gw - NE) : gw;
    const float* p = side ? g_pt : g_ph;

    int start = g_coffs[gw];
    int end = g_coffs[gw + 1];

    const float4* pn4 = (const float4*)(p + node * NHEAD);
    float4 pnA = pn4[0], pnB = pn4[1];
    float pn[NHEAD] = {pnA.x, pnA.y, pnA.z, pnA.w, pnB.x, pnB.y, pnB.z, pnB.w};

    // ---- phase 1: denominators per head -------------------------------------
    float exs[NHEAD];
#pragma unroll
    for (int h = 0; h < NHEAD; h++) exs[h] = 0.0f;
    for (int j = start + lane; j < end; j += 32) {
        int r = g_elist[j];
        const float4* pr4 = (const float4*)(g_pr + r * NHEAD);
        float4 A = pr4[0], B = pr4[1];
        exs[0] += __expf(lrelu(pn[0] + A.x));
        exs[1] += __expf(lrelu(pn[1] + A.y));
        exs[2] += __expf(lrelu(pn[2] + A.z));
        exs[3] += __expf(lrelu(pn[3] + A.w));
        exs[4] += __expf(lrelu(pn[4] + B.x));
        exs[5] += __expf(lrelu(pn[5] + B.y));
        exs[6] += __expf(lrelu(pn[6] + B.z));
        exs[7] += __expf(lrelu(pn[7] + B.w));
    }
#pragma unroll
    for (int h = 0; h < NHEAD; h++) {
        float v = exs[h];
#pragma unroll
        for (int off = 16; off > 0; off >>= 1) v += __shfl_xor_sync(0xffffffffu, v, off);
        exs[h] = v;
    }

    int myh = lane & 7;
    int myg = lane >> 3;
    float pn_my = 0.0f, den_my = 0.0f;
#pragma unroll
    for (int h = 0; h < NHEAD; h++) {
        pn_my = (myh == h) ? pn[h] : pn_my;
        den_my = (myh == h) ? exs[h] : den_my;
    }
    float invd_my = 1.0f / (den_my + 1e-16f);

    // ---- phase 2: 4 edges/iter via 8-lane groups; fp16 row gathers ----------
    float accA[8], accB[8];
#pragma unroll
    for (int i = 0; i < 8; i++) { accA[i] = 0.0f; accB[i] = 0.0f; }

#define PROC4(BASE)                                                            \
    {                                                                          \
        int r = g_elist[(BASE) + myg];                                         \
        float ex = __expf(lrelu(pn_my + g_pr[r * NHEAD + myh])) * invd_my;     \
        ex += __shfl_xor_sync(0xffffffffu, ex, 1);                             \
        ex += __shfl_xor_sync(0xffffffffu, ex, 2);                             \
        ex += __shfl_xor_sync(0xffffffffu, ex, 4);                             \
        float a = ex * 0.125f;                                                 \
        const uint4* row = g_xrh4 + r * 16;                                    \
        uint4 u0 = row[myh];                                                   \
        uint4 u1 = row[myh + 8];                                               \
        float2 q;                                                              \
        q = __half22float2(*(__half2*)&u0.x); accA[0] += a * q.x; accA[1] += a * q.y; \
        q = __half22float2(*(__half2*)&u0.y); accA[2] += a * q.x; accA[3] += a * q.y; \
        q = __half22float2(*(__half2*)&u0.z); accA[4] += a * q.x; accA[5] += a * q.y; \
        q = __half22float2(*(__half2*)&u0.w); accA[6] += a * q.x; accA[7] += a * q.y; \
        q = __half22float2(*(__half2*)&u1.x); accB[0] += a * q.x; accB[1] += a * q.y; \
        q = __half22float2(*(__half2*)&u1.y); accB[2] += a * q.x; accB[3] += a * q.y; \
        q = __half22float2(*(__half2*)&u1.z); accB[4] += a * q.x; accB[5] += a * q.y; \
        q = __half22float2(*(__half2*)&u1.w); accB[6] += a * q.x; accB[7] += a * q.y; \
    }

    int jb = start;
    for (; jb + 8 <= end; jb += 8) {
        PROC4(jb)
        PROC4(jb + 4)
    }
    if (jb + 4 <= end) {
        PROC4(jb)
        jb += 4;
    }
#undef PROC4

    // reduce accumulators across the 4 groups (xor 8, 16)
#pragma unroll
    for (int i = 0; i < 8; i++) {
        accA[i] += __shfl_xor_sync(0xffffffffu, accA[i], 8);
        accA[i] += __shfl_xor_sync(0xffffffffu, accA[i], 16);
        accB[i] += __shfl_xor_sync(0xffffffffu, accB[i], 8);
        accB[i] += __shfl_xor_sync(0xffffffffu, accB[i], 16);
    }

    // remap to per-lane float4 layout via shared staging
    if (myg == 0) {          // lanes 0..7, myh == lane
        float* so = s_out[wslot];
#pragma unroll
        for (int i = 0; i < 8; i++) so[8 * lane + i] = accA[i];
#pragma unroll
        for (int i = 0; i < 8; i++) so[64 + 8 * lane + i] = accB[i];
    }
    __syncwarp();
    float4 res = *(const float4*)&s_out[wslot][4 * lane];

    // tail (0..3 edges): whole-warp, each lane loads its own 4 columns (8B)
    for (; jb < end; jb++) {
        int r = g_elist[jb];                      // uniform -> broadcast
        float ex = __expf(lrelu(pn_my + g_pr[r * NHEAD + myh])) * invd_my;
        ex += __shfl_xor_sync(0xffffffffu, ex, 1);
        ex += __shfl_xor_sync(0xffffffffu, ex, 2);
        ex += __shfl_xor_sync(0xffffffffu, ex, 4);
        float a = ex * 0.125f;
        const uint2* row2 = (const uint2*)(g_xrh4 + r * 16);
        uint2 u = row2[lane];
        float2 qa = __half22float2(*(__half2*)&u.x);
        float2 qb = __half22float2(*(__half2*)&u.y);
        res.x += a * qa.x;
        res.y += a * qa.y;
        res.z += a * qb.x;
        res.w += a * qb.y;
    }

    // streaming store: keep hot structures resident in L2
    __stcs((float4*)(out + (long)node * (2 * DIM) + side * DIM) + lane, res);
}

// ---------------- launch ------------------------------------------------------
extern "C" void kernel_launch(void* const* d_in, const int* in_sizes, int n_in,
                              void* d_out, int out_size) {
    const float* x_e = (const float*)d_in[0];
    const float* x_r = (const float*)d_in[1];
    const float* Wh  = (const float*)d_in[2];
    const float* Wt  = (const float*)d_in[3];
    const float* Wr  = (const float*)d_in[4];
    const void*  ei  = d_in[5];
    const void*  rel = d_in[6];
    int E = in_sizes[6];          // element count of rel == number of edges

    k_prep<<<ZBLK + CVTBLK + PEBLK + PRBLK, 256>>>((const unsigned*)ei, x_e, x_r,
                                                   Wh, Wt, Wr);

    k_hist<<<(E + 255) / 256, 256>>>(ei, rel, E);

    k_scan_a<<<NTILES, 256>>>();
    k_scan_c<<<NTILES, 512>>>(E);

    k_fill<<<(E + 255) / 256, 256>>>(E);

    k_agg<<<(NSEG * 32 + 127) / 128, 128>>>((float*)d_out);
}

// round 14
// speedup vs baseline: 1.0647x; 1.0126x over previous
#include <cuda_runtime.h>
#include <cuda_bf16.h>
#include <cuda_fp16.h>
#include <cstdint>

// Problem constants (fixed by the dataset)
#define NE 50000
#define NR 2000
#define EMAX 800000
#define NHEAD 8
#define DIM 128
#define NEG_SLOPE 0.01f
#define NSEG (2 * NE)
#define TILE 512
#define NTILES ((NSEG + TILE - 1) / TILE)   // 196

// grid partition for the fused hist+prep kernel (after the hist section)
#define CVTBLK ((NR * DIM / 4 + 255) / 256) // x_r -> fp16
#define PEBLK (NE * 32 / 256)               // proj x_e
#define PRBLK (NR * 32 / 256)               // proj x_r
#define PREPBLK (CVTBLK + PEBLK + PRBLK)

// ---------------- scratch (static device globals; no allocation) -------------
// g_deg is zero on first use (BSS) and re-zeroed by k_scan_c every run.
__device__ float g_ph[NE * NHEAD];      // x_e @ Wh.T
__device__ float g_pt[NE * NHEAD];      // x_e @ Wt.T
__device__ float g_pr[NR * NHEAD];      // x_r @ Wr.T
__device__ uint4 g_xrh4[NR * DIM / 8];  // x_r in fp16, 16 uint4 (256B) per row
__device__ int   g_deg[NSEG];           // degrees: [0,NE)=h side, [NE,2NE)=t side
__device__ int   g_coffs[NSEG + 1];     // exclusive offsets (combined h|t CSR)
__device__ int   g_elist[2 * EMAX];     // rel id per slot, grouped by (side,node)
__device__ int4  g_htr[EMAX];           // (h, t, r, rank_h | rank_t<<16)
__device__ int   g_tsum[NTILES];        // per-tile degree sums
__device__ int   g_is64;                // 1 if edge_index/rel are int64

__device__ __forceinline__ float lrelu(float s) {
    return (s > 0.0f) ? s : NEG_SLOPE * s;
}

// ---------------- kernel 0: detect index width (1 block) ---------------------
__global__ void k_detect(const unsigned* __restrict__ ei_words) {
    // If int64: odd 32-bit words are the (zero) high halves of small values.
    unsigned w = ei_words[2 * threadIdx.x + 1];
    unsigned ball = __ballot_sync(0xffffffffu, w == 0u);
    if (threadIdx.x == 0) g_is64 = (ball == 0xffffffffu) ? 1 : 0;
}

// ---------------- warp-per-row projection helper ------------------------------
__device__ __forceinline__ void proj_rows(const float* __restrict__ x,
                                          const float* __restrict__ Wa,
                                          const float* __restrict__ Wb,
                                          float* pa, float* pb, int bid) {
    int w = (bid * 256 + threadIdx.x) >> 5;
    int lane = threadIdx.x & 31;
    const float* xr = x + (long)w * DIM;
    float x0 = xr[lane], x1 = xr[lane + 32], x2 = xr[lane + 64], x3 = xr[lane + 96];
#pragma unroll
    for (int h = 0; h < NHEAD; h++) {
        const float* wa = Wa + h * DIM;
        float a = x0 * wa[lane] + x1 * wa[lane + 32] + x2 * wa[lane + 64] + x3 * wa[lane + 96];
#pragma unroll
        for (int off = 16; off > 0; off >>= 1) a += __shfl_xor_sync(0xffffffffu, a, off);
        if (lane == 0) pa[w * NHEAD + h] = a;
        if (pb) {
            const float* wb = Wb + h * DIM;
            float b = x0 * wb[lane] + x1 * wb[lane + 32] + x2 * wb[lane + 64] + x3 * wb[lane + 96];
#pragma unroll
            for (int off = 16; off > 0; off >>= 1) b += __shfl_xor_sync(0xffffffffu, b, off);
            if (lane == 0) pb[w * NHEAD + h] = b;
        }
    }
}

// ---------------- kernel 1: FUSED hist + cvt + projections -------------------
// Blocks [0, histblk): edge decode + degree histogram (latency/atomic bound).
// Remaining blocks: x_r->fp16 convert + both projections (also latency bound).
// Independent work co-resident in one launch -> mutual latency hiding.
__global__ __launch_bounds__(256) void k_histprep(const void* __restrict__ ei,
                                                  const void* __restrict__ rel,
                                                  int E,
                                                  const float* __restrict__ x_e,
                                                  const float* __restrict__ x_r,
                                                  const float* __restrict__ Wh,
                                                  const float* __restrict__ Wt,
                                                  const float* __restrict__ Wr) {
    int histblk = (E + 255) >> 8;
    int bid = blockIdx.x;
    if (bid < histblk) {
        int e = bid * 256 + threadIdx.x;
        if (e >= E) return;
        int is64 = g_is64;
        int h, t, r;
        if (is64) {
            h = (int)((const long long*)ei)[e];
            t = (int)((const long long*)ei)[(long)E + e];
            r = (int)((const long long*)rel)[e];
        } else {
            h = ((const int*)ei)[e];
            t = ((const int*)ei)[(long)E + e];
            r = ((const int*)rel)[e];
        }
        int rank_h = atomicAdd(&g_deg[h], 1);
        int rank_t = atomicAdd(&g_deg[NE + t], 1);
        g_htr[e] = make_int4(h, t, r, rank_h | (rank_t << 16));
        return;
    }
    bid -= histblk;
    if (bid < CVTBLK) {
        int i = bid * 256 + threadIdx.x;
        if (i < NR * DIM / 4) {
            float4 v = ((const float4*)x_r)[i];
            __half2* dst = (__half2*)g_xrh4;
            dst[i * 2]     = __floats2half2_rn(v.x, v.y);
            dst[i * 2 + 1] = __floats2half2_rn(v.z, v.w);
        }
        return;
    }
    bid -= CVTBLK;
    if (bid < PEBLK) { proj_rows(x_e, Wh, Wt, g_ph, g_pt, bid); return; }
    bid -= PEBLK;
    proj_rows(x_r, Wr, nullptr, g_pr, nullptr, bid);
}

// ---------------- kernel 2a: per-tile degree sums -----------------------------
__global__ __launch_bounds__(256) void k_scan_a() {
    __shared__ int sh[256];
    int tid = threadIdx.x;
    int i0 = blockIdx.x * TILE + tid * 2;
    int v = 0;
    if (i0 < NSEG) v += g_deg[i0];
    if (i0 + 1 < NSEG) v += g_deg[i0 + 1];
    sh[tid] = v;
    __syncthreads();
    for (int off = 128; off > 0; off >>= 1) {
        if (tid < off) sh[tid] += sh[tid + off];
        __syncthreads();
    }
    if (tid == 0) g_tsum[blockIdx.x] = sh[0];
}

// ---------------- kernel 2b: tile scan + top-level scan + re-zero g_deg ------
__global__ __launch_bounds__(512) void k_scan_c(int E) {
    __shared__ int stop[256];
    __shared__ int stile[512];
    int tid = threadIdx.x;
    if (tid < 256) stop[tid] = (tid < NTILES) ? g_tsum[tid] : 0;
    __syncthreads();
    for (int off = 1; off < 256; off <<= 1) {
        int t = 0;
        if (tid < 256 && tid >= off) t = stop[tid - off];
        __syncthreads();
        if (tid < 256) stop[tid] += t;
        __syncthreads();
    }
    int tile_off = (blockIdx.x == 0) ? 0 : stop[blockIdx.x - 1];
    int idx = blockIdx.x * TILE + tid;
    int v = (idx < NSEG) ? g_deg[idx] : 0;
    stile[tid] = v;
    __syncthreads();
    for (int off = 1; off < 512; off <<= 1) {
        int t = 0;
        if (tid >= off) t = stile[tid - off];
        __syncthreads();
        stile[tid] += t;
        __syncthreads();
    }
    if (idx < NSEG) {
        g_coffs[idx] = tile_off + stile[tid] - v;
        g_deg[idx] = 0;          // re-zero for the next run (graph replay safe)
    }
    if (blockIdx.x == 0 && tid == 0) g_coffs[NSEG] = 2 * E;
}

// ---------------- kernel 3: rank-based scatter (NO atomics) ------------------
__global__ __launch_bounds__(256) void k_fill(int E) {
    int e = blockIdx.x * blockDim.x + threadIdx.x;
    if (e >= E) return;
    int4 v = g_htr[e];                 // (h, t, r, rank_h | rank_t<<16)
    int rh = v.w & 0xFFFF;
    int rt = v.w >> 16;
    g_elist[g_coffs[v.x] + rh] = v.z;
    g_elist[g_coffs[NE + v.y] + rt] = v.z;
}

// ---------------- kernel 4: softmax + aggregation (fp16 x_r gather) ----------
// One warp per (side, node), 128-thread blocks (byte-identical to R13).
__global__ __launch_bounds__(128) void k_agg(float* __restrict__ out) {
    __shared__ __align__(16) float s_out[4][128];
    int wslot = threadIdx.x >> 5;
    int gw = (blockIdx.x * blockDim.x + threadIdx.x) >> 5;
    int lane = threadIdx.x & 31;
    if (gw >= NSEG) return;
    int side = (gw >= NE) ? 1 : 0;
    int node = side ? (gw - NE) : gw;
    const float* p = side ? g_pt : g_ph;

    int start = g_coffs[gw];
    int end = g_coffs[gw + 1];

    const float4* pn4 = (const float4*)(p + node * NHEAD);
    float4 pnA = pn4[0], pnB = pn4[1];
    float pn[NHEAD] = {pnA.x, pnA.y, pnA.z, pnA.w, pnB.x, pnB.y, pnB.z, pnB.w};

    // ---- phase 1: denominators per head -------------------------------------
    float exs[NHEAD];
#pragma unroll
    for (int h = 0; h < NHEAD; h++) exs[h] = 0.0f;
    for (int j = start + lane; j < end; j += 32) {
        int r = g_elist[j];
        const float4* pr4 = (const float4*)(g_pr + r * NHEAD);
        float4 A = pr4[0], B = pr4[1];
        exs[0] += __expf(lrelu(pn[0] + A.x));
        exs[1] += __expf(lrelu(pn[1] + A.y));
        exs[2] += __expf(lrelu(pn[2] + A.z));
        exs[3] += __expf(lrelu(pn[3] + A.w));
        exs[4] += __expf(lrelu(pn[4] + B.x));
        exs[5] += __expf(lrelu(pn[5] + B.y));
        exs[6] += __expf(lrelu(pn[6] + B.z));
        exs[7] += __expf(lrelu(pn[7] + B.w));
    }
#pragma unroll
    for (int h = 0; h < NHEAD; h++) {
        float v = exs[h];
#pragma unroll
        for (int off = 16; off > 0; off >>= 1) v += __shfl_xor_sync(0xffffffffu, v, off);
        exs[h] = v;
    }

    int myh = lane & 7;
    int myg = lane >> 3;
    float pn_my = 0.0f, den_my = 0.0f;
#pragma unroll
    for (int h = 0; h < NHEAD; h++) {
        pn_my = (myh == h) ? pn[h] : pn_my;
        den_my = (myh == h) ? exs[h] : den_my;
    }
    float invd_my = 1.0f / (den_my + 1e-16f);

    // ---- phase 2: 4 edges/iter via 8-lane groups; fp16 row gathers ----------
    float accA[8], accB[8];
#pragma unroll
    for (int i = 0; i < 8; i++) { accA[i] = 0.0f; accB[i] = 0.0f; }

#define PROC4(BASE)                                                            \
    {                                                                          \
        int r = g_elist[(BASE) + myg];                                         \
        float ex = __expf(lrelu(pn_my + g_pr[r * NHEAD + myh])) * invd_my;     \
        ex += __shfl_xor_sync(0xffffffffu, ex, 1);                             \
        ex += __shfl_xor_sync(0xffffffffu, ex, 2);                             \
        ex += __shfl_xor_sync(0xffffffffu, ex, 4);                             \
        float a = ex * 0.125f;                                                 \
        const uint4* row = g_xrh4 + r * 16;                                    \
        uint4 u0 = row[myh];                                                   \
        uint4 u1 = row[myh + 8];                                               \
        float2 q;                                                              \
        q = __half22float2(*(__half2*)&u0.x); accA[0] += a * q.x; accA[1] += a * q.y; \
        q = __half22float2(*(__half2*)&u0.y); accA[2] += a * q.x; accA[3] += a * q.y; \
        q = __half22float2(*(__half2*)&u0.z); accA[4] += a * q.x; accA[5] += a * q.y; \
        q = __half22float2(*(__half2*)&u0.w); accA[6] += a * q.x; accA[7] += a * q.y; \
        q = __half22float2(*(__half2*)&u1.x); accB[0] += a * q.x; accB[1] += a * q.y; \
        q = __half22float2(*(__half2*)&u1.y); accB[2] += a * q.x; accB[3] += a * q.y; \
        q = __half22float2(*(__half2*)&u1.z); accB[4] += a * q.x; accB[5] += a * q.y; \
        q = __half22float2(*(__half2*)&u1.w); accB[6] += a * q.x; accB[7] += a * q.y; \
    }

    int jb = start;
    for (; jb + 8 <= end; jb += 8) {
        PROC4(jb)
        PROC4(jb + 4)
    }
    if (jb + 4 <= end) {
        PROC4(jb)
        jb += 4;
    }
#undef PROC4

    // reduce accumulators across the 4 groups (xor 8, 16)
#pragma unroll
    for (int i = 0; i < 8; i++) {
        accA[i] += __shfl_xor_sync(0xffffffffu, accA[i], 8);
        accA[i] += __shfl_xor_sync(0xffffffffu, accA[i], 16);
        accB[i] += __shfl_xor_sync(0xffffffffu, accB[i], 8);
        accB[i] += __shfl_xor_sync(0xffffffffu, accB[i], 16);
    }

    // remap to per-lane float4 layout via shared staging
    if (myg == 0) {          // lanes 0..7, myh == lane
        float* so = s_out[wslot];
#pragma unroll
        for (int i = 0; i < 8; i++) so[8 * lane + i] = accA[i];
#pragma unroll
        for (int i = 0; i < 8; i++) so[64 + 8 * lane + i] = accB[i];
    }
    __syncwarp();
    float4 res = *(const float4*)&s_out[wslot][4 * lane];

    // tail (0..3 edges): whole-warp, each lane loads its own 4 columns (8B)
    for (; jb < end; jb++) {
        int r = g_elist[jb];                      // uniform -> broadcast
        float ex = __expf(lrelu(pn_my + g_pr[r * NHEAD + myh])) * invd_my;
        ex += __shfl_xor_sync(0xffffffffu, ex, 1);
        ex += __shfl_xor_sync(0xffffffffu, ex, 2);
        ex += __shfl_xor_sync(0xffffffffu, ex, 4);
        float a = ex * 0.125f;
        const uint2* row2 = (const uint2*)(g_xrh4 + r * 16);
        uint2 u = row2[lane];
        float2 qa = __half22float2(*(__half2*)&u.x);
        float2 qb = __half22float2(*(__half2*)&u.y);
        res.x += a * qa.x;
        res.y += a * qa.y;
        res.z += a * qb.x;
        res.w += a * qb.y;
    }

    // streaming store: keep hot structures resident in L2
    __stcs((float4*)(out + (long)node * (2 * DIM) + side * DIM) + lane, res);
}

// ---------------- launch ------------------------------------------------------
extern "C" void kernel_launch(void* const* d_in, const int* in_sizes, int n_in,
                              void* d_out, int out_size) {
    const float* x_e = (const float*)d_in[0];
    const float* x_r = (const float*)d_in[1];
    const float* Wh  = (const float*)d_in[2];
    const float* Wt  = (const float*)d_in[3];
    const float* Wr  = (const float*)d_in[4];
    const void*  ei  = d_in[5];
    const void*  rel = d_in[6];
    int E = in_sizes[6];          // element count of rel == number of edges

    int histblk = (E + 255) / 256;

    // 0: tiny index-width probe (g_deg already zero: BSS first call,
    //    re-zeroed by k_scan_c on every run thereafter)
    k_detect<<<1, 32>>>((const unsigned*)ei);

    // 1: fused hist + cvt + projections (independent, mutually latency-hiding)
    k_histprep<<<histblk + PREPBLK, 256>>>(ei, rel, E, x_e, x_r, Wh, Wt, Wr);

    // 2: CSR offsets
    k_scan_a<<<NTILES, 256>>>();
    k_scan_c<<<NTILES, 512>>>(E);

    // 3: rank-based scatter
    k_fill<<<(E + 255) / 256, 256>>>(E);

    // 4: softmax + aggregation
    k_agg<<<(NSEG * 32 + 127) / 128, 128>>>((float*)d_out);
}

// round 16
// speedup vs baseline: 1.0818x; 1.0161x over previous
#include <cuda_runtime.h>
#include <cuda_bf16.h>
#include <cuda_fp16.h>
#include <cstdint>

// Problem constants (fixed by the dataset)
#define NE 50000
#define NR 2000
#define EMAX 800000
#define NHEAD 8
#define DIM 128
#define NEG_SLOPE 0.01f
#define NSEG (2 * NE)
#define TILE 512
#define NTILES ((NSEG + TILE - 1) / TILE)   // 196

// grid partition for the fused hist+prep kernel (after the hist section)
#define CVTBLK ((NR * DIM / 4 + 255) / 256) // x_r -> fp16
#define PEBLK (NE * 32 / 256)               // proj x_e
#define PRBLK (NR * 32 / 256)               // proj x_r
#define PREPBLK (CVTBLK + PEBLK + PRBLK)

// ---------------- scratch (static device globals; no allocation) -------------
// g_deg is zero on first use (BSS) and re-zeroed by k_scan_c every run.
__device__ float g_ph[NE * NHEAD];      // x_e @ Wh.T
__device__ float g_pt[NE * NHEAD];      // x_e @ Wt.T
__device__ float g_pr[NR * NHEAD];      // x_r @ Wr.T
__device__ uint4 g_xrh4[NR * DIM / 8];  // x_r in fp16, 16 uint4 (256B) per row
__device__ int   g_deg[NSEG];           // degrees: [0,NE)=h side, [NE,2NE)=t side
__device__ int   g_coffs[NSEG + 1];     // exclusive offsets (combined h|t CSR)
__device__ int   g_elist[2 * EMAX];     // rel id per slot, grouped by (side,node)
__device__ int4  g_htr[EMAX];           // (h, t, r, rank_h | rank_t<<16)
__device__ int   g_tsum[NTILES];        // per-tile degree sums

__device__ __forceinline__ float lrelu(float s) {
    return (s > 0.0f) ? s : NEG_SLOPE * s;
}

// ---------------- warp-per-row projection helper ------------------------------
__device__ __forceinline__ void proj_rows(const float* __restrict__ x,
                                          const float* __restrict__ Wa,
                                          const float* __restrict__ Wb,
                                          float* pa, float* pb, int bid) {
    int w = (bid * 256 + threadIdx.x) >> 5;
    int lane = threadIdx.x & 31;
    const float* xr = x + (long)w * DIM;
    float x0 = xr[lane], x1 = xr[lane + 32], x2 = xr[lane + 64], x3 = xr[lane + 96];
#pragma unroll
    for (int h = 0; h < NHEAD; h++) {
        const float* wa = Wa + h * DIM;
        float a = x0 * wa[lane] + x1 * wa[lane + 32] + x2 * wa[lane + 64] + x3 * wa[lane + 96];
#pragma unroll
        for (int off = 16; off > 0; off >>= 1) a += __shfl_xor_sync(0xffffffffu, a, off);
        if (lane == 0) pa[w * NHEAD + h] = a;
        if (pb) {
            const float* wb = Wb + h * DIM;
            float b = x0 * wb[lane] + x1 * wb[lane + 32] + x2 * wb[lane + 64] + x3 * wb[lane + 96];
#pragma unroll
            for (int off = 16; off > 0; off >>= 1) b += __shfl_xor_sync(0xffffffffu, b, off);
            if (lane == 0) pb[w * NHEAD + h] = b;
        }
    }
}

// ---------------- kernel 1: FUSED hist + cvt + projections -------------------
// Hist blocks compute the int64/int32 width probe per-warp (L1-hit loads of the
// first 64 words) -- no separate detect kernel, no global flag, no extra dep.
__global__ __launch_bounds__(256) void k_histprep(const void* __restrict__ ei,
                                                  const void* __restrict__ rel,
                                                  int E,
                                                  const float* __restrict__ x_e,
                                                  const float* __restrict__ x_r,
                                                  const float* __restrict__ Wh,
                                                  const float* __restrict__ Wt,
                                                  const float* __restrict__ Wr) {
    int histblk = (E + 255) >> 8;
    int bid = blockIdx.x;
    if (bid < histblk) {
        // per-warp width probe: if int64, odd words of edge_index are all zero
        unsigned pw = ((const unsigned*)ei)[2 * (threadIdx.x & 31) + 1];
        int is64 = (__ballot_sync(0xffffffffu, pw == 0u) == 0xffffffffu);

        int e = bid * 256 + threadIdx.x;
        if (e >= E) return;
        int h, t, r;
        if (is64) {
            h = (int)((const long long*)ei)[e];
            t = (int)((const long long*)ei)[(long)E + e];
            r = (int)((const long long*)rel)[e];
        } else {
            h = ((const int*)ei)[e];
            t = ((const int*)ei)[(long)E + e];
            r = ((const int*)rel)[e];
        }
        int rank_h = atomicAdd(&g_deg[h], 1);
        int rank_t = atomicAdd(&g_deg[NE + t], 1);
        g_htr[e] = make_int4(h, t, r, rank_h | (rank_t << 16));
        return;
    }
    bid -= histblk;
    if (bid < CVTBLK) {
        int i = bid * 256 + threadIdx.x;
        if (i < NR * DIM / 4) {
            float4 v = ((const float4*)x_r)[i];
            __half2* dst = (__half2*)g_xrh4;
            dst[i * 2]     = __floats2half2_rn(v.x, v.y);
            dst[i * 2 + 1] = __floats2half2_rn(v.z, v.w);
        }
        return;
    }
    bid -= CVTBLK;
    if (bid < PEBLK) { proj_rows(x_e, Wh, Wt, g_ph, g_pt, bid); return; }
    bid -= PEBLK;
    proj_rows(x_r, Wr, nullptr, g_pr, nullptr, bid);
}

// ---------------- kernel 2a: per-tile degree sums -----------------------------
__global__ __launch_bounds__(256) void k_scan_a() {
    __shared__ int sh[256];
    int tid = threadIdx.x;
    int i0 = blockIdx.x * TILE + tid * 2;
    int v = 0;
    if (i0 < NSEG) v += g_deg[i0];
    if (i0 + 1 < NSEG) v += g_deg[i0 + 1];
    sh[tid] = v;
    __syncthreads();
    for (int off = 128; off > 0; off >>= 1) {
        if (tid < off) sh[tid] += sh[tid + off];
        __syncthreads();
    }
    if (tid == 0) g_tsum[blockIdx.x] = sh[0];
}

// ---------------- kernel 2b: tile scan + top-level scan + re-zero g_deg ------
__global__ __launch_bounds__(512) void k_scan_c(int E) {
    __shared__ int stop[256];
    __shared__ int stile[512];
    int tid = threadIdx.x;
    if (tid < 256) stop[tid] = (tid < NTILES) ? g_tsum[tid] : 0;
    __syncthreads();
    for (int off = 1; off < 256; off <<= 1) {
        int t = 0;
        if (tid < 256 && tid >= off) t = stop[tid - off];
        __syncthreads();
        if (tid < 256) stop[tid] += t;
        __syncthreads();
    }
    int tile_off = (blockIdx.x == 0) ? 0 : stop[blockIdx.x - 1];
    int idx = blockIdx.x * TILE + tid;
    int v = (idx < NSEG) ? g_deg[idx] : 0;
    stile[tid] = v;
    __syncthreads();
    for (int off = 1; off < 512; off <<= 1) {
        int t = 0;
        if (tid >= off) t = stile[tid - off];
        __syncthreads();
        stile[tid] += t;
        __syncthreads();
    }
    if (idx < NSEG) {
        g_coffs[idx] = tile_off + stile[tid] - v;
        g_deg[idx] = 0;          // re-zero for the next run (graph replay safe)
    }
    if (blockIdx.x == 0 && tid == 0) g_coffs[NSEG] = 2 * E;
}

// ---------------- kernel 3: rank-based scatter (NO atomics) ------------------
__global__ __launch_bounds__(256) void k_fill(int E) {
    int e = blockIdx.x * blockDim.x + threadIdx.x;
    if (e >= E) return;
    int4 v = g_htr[e];                 // (h, t, r, rank_h | rank_t<<16)
    int rh = v.w & 0xFFFF;
    int rt = v.w >> 16;
    g_elist[g_coffs[v.x] + rh] = v.z;
    g_elist[g_coffs[NE + v.y] + rt] = v.z;
}

// ---------------- kernel 4: softmax + aggregation (fp16 gather + FFMA2) ------
// One warp per (side, node), 128-thread blocks. Phase-2 accumulation uses
// packed fma.rn.f32x2 (Blackwell FFMA2, PTX-only): 2 FFMA -> 1 FFMA2 per half2.
__global__ __launch_bounds__(128) void k_agg(float* __restrict__ out) {
    __shared__ __align__(16) float s_out[4][128];
    int wslot = threadIdx.x >> 5;
    int gw = (blockIdx.x * blockDim.x + threadIdx.x) >> 5;
    int lane = threadIdx.x & 31;
    if (gw >= NSEG) return;
    int side = (gw >= NE) ? 1 : 0;
    int node = side ? (gw - NE) : gw;
    const float* p = side ? g_pt : g_ph;

    int start = g_coffs[gw];
    int end = g_coffs[gw + 1];

    const float4* pn4 = (const float4*)(p + node * NHEAD);
    float4 pnA = pn4[0], pnB = pn4[1];
    float pn[NHEAD] = {pnA.x, pnA.y, pnA.z, pnA.w, pnB.x, pnB.y, pnB.z, pnB.w};

    // ---- phase 1: denominators per head -------------------------------------
    float exs[NHEAD];
#pragma unroll
    for (int h = 0; h < NHEAD; h++) exs[h] = 0.0f;
    for (int j = start + lane; j < end; j += 32) {
        int r = g_elist[j];
        const float4* pr4 = (const float4*)(g_pr + r * NHEAD);
        float4 A = pr4[0], B = pr4[1];
        exs[0] += __expf(lrelu(pn[0] + A.x));
        exs[1] += __expf(lrelu(pn[1] + A.y));
        exs[2] += __expf(lrelu(pn[2] + A.z));
        exs[3] += __expf(lrelu(pn[3] + A.w));
        exs[4] += __expf(lrelu(pn[4] + B.x));
        exs[5] += __expf(lrelu(pn[5] + B.y));
        exs[6] += __expf(lrelu(pn[6] + B.z));
        exs[7] += __expf(lrelu(pn[7] + B.w));
    }
#pragma unroll
    for (int h = 0; h < NHEAD; h++) {
        float v = exs[h];
#pragma unroll
        for (int off = 16; off > 0; off >>= 1) v += __shfl_xor_sync(0xffffffffu, v, off);
        exs[h] = v;
    }

    int myh = lane & 7;
    int myg = lane >> 3;
    float pn_my = 0.0f, den_my = 0.0f;
#pragma unroll
    for (int h = 0; h < NHEAD; h++) {
        pn_my = (myh == h) ? pn[h] : pn_my;
        den_my = (myh == h) ? exs[h] : den_my;
    }
    float invd_my = 1.0f / (den_my + 1e-16f);

    // ---- phase 2: 4 edges/iter via 8-lane groups; fp16 gathers + FFMA2 ------
    unsigned long long accA2[4], accB2[4];
#pragma unroll
    for (int i = 0; i < 4; i++) { accA2[i] = 0ull; accB2[i] = 0ull; }

#define FMA2(ACC, H2)                                                          \
    {                                                                          \
        float2 f = __half22float2(*(__half2*)&(H2));                           \
        unsigned long long q;                                                  \
        asm("mov.b64 %0, {%1, %2};" : "=l"(q) : "f"(f.x), "f"(f.y));           \
        asm("fma.rn.f32x2 %0, %1, %2, %3;"                                     \
            : "=l"(ACC) : "l"(q), "l"(a2), "l"(ACC));                          \
    }

#define PROC4(BASE)                                                            \
    {                                                                          \
        int r = g_elist[(BASE) + myg];                                         \
        float ex = __expf(lrelu(pn_my + g_pr[r * NHEAD + myh])) * invd_my;     \
        ex += __shfl_xor_sync(0xffffffffu, ex, 1);                             \
        ex += __shfl_xor_sync(0xffffffffu, ex, 2);                             \
        ex += __shfl_xor_sync(0xffffffffu, ex, 4);                             \
        float a = ex * 0.125f;                                                 \
        unsigned long long a2;                                                 \
        asm("mov.b64 %0, {%1, %1};" : "=l"(a2) : "f"(a));                      \
        const uint4* row = g_xrh4 + r * 16;                                    \
        uint4 u0 = row[myh];                                                   \
        uint4 u1 = row[myh + 8];                                               \
        FMA2(accA2[0], u0.x) FMA2(accA2[1], u0.y)                              \
        FMA2(accA2[2], u0.z) FMA2(accA2[3], u0.w)                              \
        FMA2(accB2[0], u1.x) FMA2(accB2[1], u1.y)                              \
        FMA2(accB2[2], u1.z) FMA2(accB2[3], u1.w)                              \
    }

    int jb = start;
    for (; jb + 8 <= end; jb += 8) {
        PROC4(jb)
        PROC4(jb + 4)
    }
    if (jb + 4 <= end) {
        PROC4(jb)
        jb += 4;
    }
#undef PROC4
#undef FMA2

    // unpack packed accumulators
    float accA[8], accB[8];
#pragma unroll
    for (int i = 0; i < 4; i++) {
        asm("mov.b64 {%0, %1}, %2;" : "=f"(accA[2 * i]), "=f"(accA[2 * i + 1])
            : "l"(accA2[i]));
        asm("mov.b64 {%0, %1}, %2;" : "=f"(accB[2 * i]), "=f"(accB[2 * i + 1])
            : "l"(accB2[i]));
    }

    // reduce accumulators across the 4 groups (xor 8, 16)
#pragma unroll
    for (int i = 0; i < 8; i++) {
        accA[i] += __shfl_xor_sync(0xffffffffu, accA[i], 8);
        accA[i] += __shfl_xor_sync(0xffffffffu, accA[i], 16);
        accB[i] += __shfl_xor_sync(0xffffffffu, accB[i], 8);
        accB[i] += __shfl_xor_sync(0xffffffffu, accB[i], 16);
    }

    // remap to per-lane float4 layout via shared staging
    if (myg == 0) {          // lanes 0..7, myh == lane
        float* so = s_out[wslot];
#pragma unroll
        for (int i = 0; i < 8; i++) so[8 * lane + i] = accA[i];
#pragma unroll
        for (int i = 0; i < 8; i++) so[64 + 8 * lane + i] = accB[i];
    }
    __syncwarp();
    float4 res = *(const float4*)&s_out[wslot][4 * lane];

    // tail (0..3 edges): whole-warp, each lane loads its own 4 columns (8B)
    for (; jb < end; jb++) {
        int r = g_elist[jb];                      // uniform -> broadcast
        float ex = __expf(lrelu(pn_my + g_pr[r * NHEAD + myh])) * invd_my;
        ex += __shfl_xor_sync(0xffffffffu, ex, 1);
        ex += __shfl_xor_sync(0xffffffffu, ex, 2);
        ex += __shfl_xor_sync(0xffffffffu, ex, 4);
        float a = ex * 0.125f;
        const uint2* row2 = (const uint2*)(g_xrh4 + r * 16);
        uint2 u = row2[lane];
        float2 qa = __half22float2(*(__half2*)&u.x);
        float2 qb = __half22float2(*(__half2*)&u.y);
        res.x += a * qa.x;
        res.y += a * qa.y;
        res.z += a * qb.x;
        res.w += a * qb.y;
    }

    // streaming store: keep hot structures resident in L2
    __stcs((float4*)(out + (long)node * (2 * DIM) + side * DIM) + lane, res);
}

// ---------------- launch ------------------------------------------------------
extern "C" void kernel_launch(void* const* d_in, const int* in_sizes, int n_in,
                              void* d_out, int out_size) {
    const float* x_e = (const float*)d_in[0];
    const float* x_r = (const float*)d_in[1];
    const float* Wh  = (const float*)d_in[2];
    const float* Wt  = (const float*)d_in[3];
    const float* Wr  = (const float*)d_in[4];
    const void*  ei  = d_in[5];
    const void*  rel = d_in[6];
    int E = in_sizes[6];          // element count of rel == number of edges

    int histblk = (E + 255) / 256;

    // 1: fused hist + cvt + projections (width probe is per-warp, no detect)
    k_histprep<<<histblk + PREPBLK, 256>>>(ei, rel, E, x_e, x_r, Wh, Wt, Wr);

    // 2: CSR offsets
    k_scan_a<<<NTILES, 256>>>();
    k_scan_c<<<NTILES, 512>>>(E);

    // 3: rank-based scatter
    k_fill<<<(E + 255) / 256, 256>>>(E);

    // 4: softmax + aggregation
    k_agg<<<(NSEG * 32 + 127) / 128, 128>>>((float*)d_out);
}